// round 1
// baseline (speedup 1.0000x reference)
#include <cuda_runtime.h>

// ---- problem constants (hardcoded in reference module) ----
#define NN 57254
#define EE 916064
#define DD 128
#define HH 8
#define BT 32768            // B*T = 64*512
#define NB_SCAN 56          // ceil(NN/1024)

// ---- device scratch (static: no allocation allowed) ----
__device__ float g_h0[NN * DD];
__device__ float g_h1[NN * DD];
__device__ float g_z [NN * DD];
__device__ float g_el[NN * HH];
__device__ float g_er[NN * HH];
__device__ int   g_rowptr[NN + 1];
__device__ int   g_cnt[NN];
__device__ int   g_csrc[EE];
__device__ int   g_bsum[64];

// ---------------------------------------------------------------------------
// h[n] = emb[n_feat[n]]   (float4 per lane)
// ---------------------------------------------------------------------------
__global__ void k_gather(const float4* __restrict__ emb,
                         const int* __restrict__ nf,
                         float4* __restrict__ h) {
    int i = blockIdx.x * blockDim.x + threadIdx.x;   // over NN*32 float4s
    if (i >= NN * 32) return;
    int n = i >> 5, l = i & 31;
    h[n * 32 + l] = emb[(long)nf[n] * 32 + l];
}

// ---------------------------------------------------------------------------
// CSR build: count, scan (3 kernels), scatter
// ---------------------------------------------------------------------------
__global__ void k_count(const int* __restrict__ dst) {
    int i = blockIdx.x * blockDim.x + threadIdx.x;
    if (i < EE) atomicAdd(&g_cnt[dst[i]], 1);
}

__global__ void k_scan1() {
    __shared__ int swsum[32];
    int t = threadIdx.x;
    int gid = blockIdx.x * 1024 + t;
    int v = (gid < NN) ? g_cnt[gid] : 0;
    int lane = t & 31, wid = t >> 5;
    int val = v;
    #pragma unroll
    for (int o = 1; o < 32; o <<= 1) {
        int u = __shfl_up_sync(0xffffffffu, val, o);
        if (lane >= o) val += u;
    }
    if (lane == 31) swsum[wid] = val;
    __syncthreads();
    if (wid == 0) {
        int wv = swsum[lane];
        #pragma unroll
        for (int o = 1; o < 32; o <<= 1) {
            int u = __shfl_up_sync(0xffffffffu, wv, o);
            if (lane >= o) wv += u;
        }
        swsum[lane] = wv;   // inclusive warp-sums scan
    }
    __syncthreads();
    int excl = val - v + (wid > 0 ? swsum[wid - 1] : 0);
    if (gid < NN) g_rowptr[gid] = excl;
    if (t == 1023) g_bsum[blockIdx.x] = excl + v;   // block total
}

__global__ void k_scan2() {
    if (threadIdx.x == 0) {
        int acc = 0;
        for (int i = 0; i < NB_SCAN; i++) { int t = g_bsum[i]; g_bsum[i] = acc; acc += t; }
    }
}

__global__ void k_scan3() {
    int gid = blockIdx.x * 1024 + threadIdx.x;
    if (gid < NN) g_rowptr[gid] += g_bsum[blockIdx.x];
    if (gid == 0) g_rowptr[NN] = EE;
}

__global__ void k_scatter(const int* __restrict__ src, const int* __restrict__ dst) {
    int i = blockIdx.x * blockDim.x + threadIdx.x;
    if (i >= EE) return;
    int d = dst[i];
    int pos = g_rowptr[d] + atomicAdd(&g_cnt[d], 1);
    g_csrc[pos] = src[i];
}

// ---------------------------------------------------------------------------
// z = h @ W   (NNx128 @ 128x128, fp32). 32-row tile, 256 threads,
// k-chunked shared (20 KB), 4x4 register tile per thread.
// ---------------------------------------------------------------------------
__global__ __launch_bounds__(256) void k_gemm(const float* __restrict__ h,
                                              const float* __restrict__ W,
                                              float* __restrict__ z) {
    __shared__ float sW[32 * 128];
    __shared__ float sH[32 * 32];
    int t = threadIdx.x;
    int rowbase = blockIdx.x * 32;
    int tcol  = t & 31;    // owns cols 4*tcol .. 4*tcol+3
    int tnode = t >> 5;    // owns nodes tnode*4 .. tnode*4+3
    float acc[4][4] = {};

    for (int kb = 0; kb < 128; kb += 32) {
        #pragma unroll
        for (int r = 0; r < 4; r++) {
            int idx = t + r * 256;                       // float4 index over 4096 floats
            ((float4*)sW)[idx] = ((const float4*)(W + kb * 128))[idx];
        }
        {
            int node = t >> 3, k4 = (t & 7) * 4;
            int row = rowbase + node;
            float4 v = make_float4(0.f, 0.f, 0.f, 0.f);
            if (row < NN) v = *(const float4*)(h + row * 128 + kb + k4);
            *(float4*)(sH + node * 32 + k4) = v;
        }
        __syncthreads();
        #pragma unroll
        for (int kk = 0; kk < 32; kk++) {
            float4 w = *(float4*)(sW + kk * 128 + tcol * 4);
            #pragma unroll
            for (int i = 0; i < 4; i++) {
                float hv = sH[(tnode * 4 + i) * 32 + kk];
                acc[i][0] += hv * w.x; acc[i][1] += hv * w.y;
                acc[i][2] += hv * w.z; acc[i][3] += hv * w.w;
            }
        }
        __syncthreads();
    }
    #pragma unroll
    for (int i = 0; i < 4; i++) {
        int row = rowbase + tnode * 4 + i;
        if (row < NN)
            *(float4*)(z + row * 128 + tcol * 4) =
                make_float4(acc[i][0], acc[i][1], acc[i][2], acc[i][3]);
    }
}

// ---------------------------------------------------------------------------
// el[n,h] = sum_o z[n,h,o]*al[h,o];  er likewise
// ---------------------------------------------------------------------------
__global__ void k_scores(const float* __restrict__ z,
                         const float* __restrict__ al,
                         const float* __restrict__ ar,
                         float* __restrict__ el,
                         float* __restrict__ er) {
    int i = blockIdx.x * blockDim.x + threadIdx.x;
    if (i >= NN * HH) return;
    int n = i >> 3, hd = i & 7;
    const float4* zp  = (const float4*)(z + n * 128 + hd * 16);
    const float4* alp = (const float4*)(al + hd * 16);
    const float4* arp = (const float4*)(ar + hd * 16);
    float sl = 0.f, sr = 0.f;
    #pragma unroll
    for (int j = 0; j < 4; j++) {
        float4 zz = zp[j], a = alp[j], r = arp[j];
        sl += zz.x * a.x + zz.y * a.y + zz.z * a.z + zz.w * a.w;
        sr += zz.x * r.x + zz.y * r.y + zz.z * r.z + zz.w * r.w;
    }
    el[i] = sl;
    er[i] = sr;
}

// ---------------------------------------------------------------------------
// Per-dst-node edge softmax + aggregate + residual + bias (+ leaky_relu).
// Segment-max dropped (cancels in alpha = a/s; scores are O(1e-2)).
// One warp per node; lane l handles dims 4l..4l+3 (head = l>>2).
// Single pass: s += a; acc += a*z[src]; then acc/s.
// ---------------------------------------------------------------------------
__global__ __launch_bounds__(256) void k_aggregate(const float* __restrict__ z,
                                                   const float* __restrict__ el,
                                                   const float* __restrict__ er,
                                                   const float* __restrict__ hin,
                                                   const float* __restrict__ bias,
                                                   float* __restrict__ hout,
                                                   int activate) {
    int warp = (blockIdx.x * blockDim.x + threadIdx.x) >> 5;
    int lane = threadIdx.x & 31;
    if (warp >= NN) return;
    int n = warp;
    int hd = lane >> 2;
    float erh = er[n * 8 + hd];
    int beg = g_rowptr[n], end = g_rowptr[n + 1];
    const float4* z4 = (const float4*)z;
    float s = 0.f;
    float4 acc = make_float4(0.f, 0.f, 0.f, 0.f);
    for (int e = beg; e < end; e++) {
        int sr = g_csrc[e];
        float x = el[sr * 8 + hd] + erh;
        x = x > 0.f ? x : 0.2f * x;          // leaky_relu slope 0.2
        float a = __expf(x);
        s += a;
        float4 zz = z4[sr * 32 + lane];
        acc.x += a * zz.x; acc.y += a * zz.y;
        acc.z += a * zz.z; acc.w += a * zz.w;
    }
    float inv = (s > 0.f) ? (1.f / s) : 0.f;
    float4 hv = ((const float4*)hin)[n * 32 + lane];
    float4 bv = ((const float4*)bias)[lane];
    float4 o;
    o.x = acc.x * inv + hv.x + bv.x;
    o.y = acc.y * inv + hv.y + bv.y;
    o.z = acc.z * inv + hv.z + bv.z;
    o.w = acc.w * inv + hv.w + bv.w;
    if (activate) {
        o.x = o.x > 0.f ? o.x : 0.01f * o.x;
        o.y = o.y > 0.f ? o.y : 0.01f * o.y;
        o.z = o.z > 0.f ? o.z : 0.01f * o.z;
        o.w = o.w > 0.f ? o.w : 0.01f * o.w;
    }
    ((float4*)hout)[n * 32 + lane] = o;
}

// ---------------------------------------------------------------------------
// out[i] = normalize(h[x[i]])  -- one warp per (b,t)
// ---------------------------------------------------------------------------
__global__ void k_output(const float* __restrict__ h,
                         const int* __restrict__ x,
                         float* __restrict__ out) {
    int warp = (blockIdx.x * blockDim.x + threadIdx.x) >> 5;
    int lane = threadIdx.x & 31;
    if (warp >= BT) return;
    int idx = x[warp];
    float4 v = ((const float4*)h)[idx * 32 + lane];
    float ss = v.x * v.x + v.y * v.y + v.z * v.z + v.w * v.w;
    #pragma unroll
    for (int o = 16; o; o >>= 1) ss += __shfl_xor_sync(0xffffffffu, ss, o);
    float nrm = sqrtf(ss);
    float inv = 1.f / fmaxf(nrm, 1e-5f);
    float4 o4 = make_float4(v.x * inv, v.y * inv, v.z * inv, v.w * inv);
    ((float4*)out)[warp * 32 + lane] = o4;
}

// ---------------------------------------------------------------------------
// host launch
// ---------------------------------------------------------------------------
extern "C" void kernel_launch(void* const* d_in, const int* in_sizes, int n_in,
                              void* d_out, int out_size) {
    const float* emb = (const float*)d_in[0];
    const float* W0  = (const float*)d_in[1];
    const float* al0 = (const float*)d_in[2];
    const float* ar0 = (const float*)d_in[3];
    const float* b0  = (const float*)d_in[4];
    const float* W1  = (const float*)d_in[5];
    const float* al1 = (const float*)d_in[6];
    const float* ar1 = (const float*)d_in[7];
    const float* b1  = (const float*)d_in[8];
    const int*   nf  = (const int*)d_in[9];
    const int*   src = (const int*)d_in[10];
    const int*   dst = (const int*)d_in[11];
    const int*   x   = (const int*)d_in[12];
    float* out = (float*)d_out;

    float *h0, *h1, *z, *el, *er;
    int *cnt;
    cudaGetSymbolAddress((void**)&h0, g_h0);
    cudaGetSymbolAddress((void**)&h1, g_h1);
    cudaGetSymbolAddress((void**)&z,  g_z);
    cudaGetSymbolAddress((void**)&el, g_el);
    cudaGetSymbolAddress((void**)&er, g_er);
    cudaGetSymbolAddress((void**)&cnt, g_cnt);

    const int T256 = 256;
    int gbNodeWarp = (NN * 32 + T256 - 1) / T256;   // warp-per-node kernels
    int gbE        = (EE + T256 - 1) / T256;
    int gbGemm     = (NN + 31) / 32;
    int gbScores   = (NN * HH + T256 - 1) / T256;
    int gbOut      = (BT * 32 + T256 - 1) / T256;

    // CSR build (dst identical across both layers -> build once)
    cudaMemsetAsync(cnt, 0, NN * sizeof(int));
    k_count<<<gbE, T256>>>(dst);
    k_scan1<<<NB_SCAN, 1024>>>();
    k_scan2<<<1, 32>>>();
    k_scan3<<<NB_SCAN, 1024>>>();
    cudaMemsetAsync(cnt, 0, NN * sizeof(int));
    k_scatter<<<gbE, T256>>>(src, dst);

    // embedding gather
    k_gather<<<gbNodeWarp, T256>>>((const float4*)emb, nf, (float4*)h0);

    // layer 0 (activation)
    k_gemm<<<gbGemm, T256>>>(h0, W0, z);
    k_scores<<<gbScores, T256>>>(z, al0, ar0, el, er);
    k_aggregate<<<gbNodeWarp, T256>>>(z, el, er, h0, b0, h1, 1);

    // layer 1 (no activation)
    k_gemm<<<gbGemm, T256>>>(h1, W1, z);
    k_scores<<<gbScores, T256>>>(z, al1, ar1, el, er);
    k_aggregate<<<gbNodeWarp, T256>>>(z, el, er, h1, b1, h0, 0);

    // normalize + final gather
    k_output<<<gbOut, T256>>>(h0, x, out);
}